// round 5
// baseline (speedup 1.0000x reference)
#include <cuda_runtime.h>
#include <cuda_bf16.h>
#include <cstdint>

#define BB 16
#define CIN 3
#define HH 256
#define WW 256
#define COUT 64
#define NPIX (BB*HH*WW)
#define PLANE (HH*WW)
#define NBLK (BB*HH)              // 4096 row-blocks

typedef unsigned long long ull;

// BN partials: [channel][32]  (16 batches x 2 half-planes)
__device__ float g_partS[COUT * 32];
__device__ float g_partQ[COUT * 32];
__device__ float g_scale[COUT];
__device__ float g_shift[COUT];

__device__ __forceinline__ void fma2(ull& a, ull b, ull c) {
    asm("fma.rn.f32x2 %0, %1, %2, %0;" : "+l"(a) : "l"(b), "l"(c));
}
__device__ __forceinline__ ull add2(ull a, ull b) {
    ull r; asm("add.rn.f32x2 %0, %1, %2;" : "=l"(r) : "l"(a), "l"(b)); return r;
}
__device__ __forceinline__ ull dup2(float w) {
    ull r; asm("mov.b64 %0, {%1, %1};" : "=l"(r) : "r"(__float_as_uint(w))); return r;
}
__device__ __forceinline__ ull pack2(float a, float b) {
    ull r; asm("mov.b64 %0, {%1, %2};" : "=l"(r) : "r"(__float_as_uint(a)), "r"(__float_as_uint(b))); return r;
}
__device__ __forceinline__ float lo32(ull v) { return __uint_as_float((unsigned)v); }
__device__ __forceinline__ float hi32(ull v) { return __uint_as_float((unsigned)(v >> 32)); }

// Consume one tap: acc[i] holds channels (2i, 2i+1). Weights for this tap are
// 64 contiguous floats at wk; all lanes read the same address (broadcast).
__device__ __forceinline__ void consume_tap(const float* __restrict__ wk,
                                            float tap, ull* acc)
{
    const ull td = dup2(tap);
    const ulonglong2* wp = reinterpret_cast<const ulonglong2*>(wk);
    #pragma unroll
    for (int j = 0; j < 16; j++) {
        ulonglong2 wv = wp[j];
        fma2(acc[2*j],   wv.x, td);
        fma2(acc[2*j+1], wv.y, td);
    }
}

// ---------------------------------------------------------------------------
// Kernel A: fully fused, single pass. One block = one (b,h) row, thread=pixel.
// Taps stay in registers; weights broadcast from SMEM; 64ch accumulated as
// 32 f32x2 pairs per thread.
// ---------------------------------------------------------------------------
__global__ __launch_bounds__(256, 2)
void fused_main(const float* __restrict__ x,
                const float* __restrict__ w_off,
                const float* __restrict__ b_off,
                const float* __restrict__ w_dcn,
                const float* __restrict__ w_conv,
                const float* __restrict__ b_conv,
                float* __restrict__ out)
{
    __shared__ float s_w[54*64];       // [k][c], tap-major
    __shared__ float s_woff[18*32];    // padded rows (cols 27..31 = 0)
    __shared__ ull   s_bpair[32];      // (b[2i], b[2i+1])
    __shared__ float s_boff[18];
    __shared__ float s_x[3*3*264];     // [ci][row][col+1], rows h-1..h+1

    const int tid  = threadIdx.x;
    const int bidx = blockIdx.x;
    const int b    = bidx >> 8;
    const int h    = bidx & 255;

    for (int i = tid; i < 54*64; i += 256) {
        int k = i >> 6, c = i & 63;
        s_w[i] = (k < 27) ? w_conv[c*27 + k] : w_dcn[c*27 + (k - 27)];
    }
    for (int i = tid; i < 18*32; i += 256) {
        int o = i >> 5, j = i & 31;
        s_woff[i] = (j < 27) ? w_off[o*27 + j] : 0.f;
    }
    if (tid < 32) s_bpair[tid] = pack2(b_conv[2*tid], b_conv[2*tid+1]);
    if (tid < 18) s_boff[tid] = b_off[tid];

    for (int i = tid; i < 3*3*258; i += 256) {
        int ci = i / (3*258);
        int r  = (i / 258) % 3;
        int cc = i % 258;
        int gy = h - 1 + r;
        int gx = cc - 1;
        float v = 0.f;
        if (gy >= 0 && gy < HH && gx >= 0 && gx < WW)
            v = x[((size_t)(b*3 + ci)*HH + gy)*WW + gx];
        s_x[(ci*3 + r)*264 + cc] = v;
    }
    __syncthreads();

    const int w = tid;

    ull acc[32];
    #pragma unroll
    for (int i = 0; i < 32; i++) acc[i] = 0ULL;

    // ---- pack im2col taps for the offset conv (f32x2 pairs, pad to 14) ----
    ull fvp[14];
    {
        float tv[27];
        #pragma unroll
        for (int ci = 0; ci < 3; ci++)
            #pragma unroll
            for (int kp = 0; kp < 9; kp++)
                tv[ci*9 + kp] = s_x[(ci*3 + kp/3)*264 + w + (kp%3)];
        #pragma unroll
        for (int q = 0; q < 13; q++) fvp[q] = pack2(tv[2*q], tv[2*q+1]);
        fvp[13] = pack2(tv[26], 0.f);
    }

    // ---- consume the 27 im2col taps (rolled loops: tiny icache body) ----
    {
        const float* wk = s_w;
        for (int ci = 0; ci < 3; ci++) {
            const float* xr = s_x + ci*792 + w;
            for (int r = 0; r < 3; r++) {
                #pragma unroll
                for (int cc = 0; cc < 3; cc++) {
                    consume_tap(wk, xr[r*264 + cc], acc);
                    wk += 64;
                }
            }
        }
    }

    // ---- per kernel tap: offset conv -> bilinear sample -> consume ----
    const float* xb = x + (size_t)b * 3 * PLANE;
    #pragma unroll 1
    for (int k = 0; k < 9; k++) {
        // offset conv (vectorized over 14 tap-pairs)
        ull ay = 0ULL, ax = 0ULL;
        const ulonglong2* wyp = reinterpret_cast<const ulonglong2*>(s_woff + (2*k)*32);
        const ulonglong2* wxp = reinterpret_cast<const ulonglong2*>(s_woff + (2*k+1)*32);
        #pragma unroll
        for (int v = 0; v < 7; v++) {
            ulonglong2 a = wyp[v];
            ulonglong2 c = wxp[v];
            fma2(ay, a.x, fvp[2*v]);
            fma2(ay, a.y, fvp[2*v+1]);
            fma2(ax, c.x, fvp[2*v]);
            fma2(ax, c.y, fvp[2*v+1]);
        }
        float dy = lo32(ay) + hi32(ay) + s_boff[2*k];
        float dx = lo32(ax) + hi32(ax) + s_boff[2*k+1];

        const int ky = k / 3, kx = k - 3*ky;
        float py = (float)(h + ky - 1) + dy;
        float px = (float)(w + kx - 1) + dx;
        float y0 = floorf(py), x0 = floorf(px);
        float ly = py - y0,    lx = px - x0;
        float hy = 1.f - ly,   hx = 1.f - lx;
        float y1 = y0 + 1.f,   x1 = x0 + 1.f;
        bool vy0 = (y0 >= 0.f) && (y0 <= 255.f);
        bool vy1 = (y1 >= 0.f) && (y1 <= 255.f);
        bool vx0 = (x0 >= 0.f) && (x0 <= 255.f);
        bool vx1 = (x1 >= 0.f) && (x1 <= 255.f);
        float w00 = hy*hx * ((vy0 && vx0) ? 1.f : 0.f);
        float w01 = hy*lx * ((vy0 && vx1) ? 1.f : 0.f);
        float w10 = ly*hx * ((vy1 && vx0) ? 1.f : 0.f);
        float w11 = ly*lx * ((vy1 && vx1) ? 1.f : 0.f);
        int iy0 = min(max((int)y0, 0), 255);
        int iy1 = min(max((int)y1, 0), 255);
        int ix0 = min(max((int)x0, 0), 255);
        int ix1 = min(max((int)x1, 0), 255);
        int i00 = iy0*WW + ix0, i01 = iy0*WW + ix1;
        int i10 = iy1*WW + ix0, i11 = iy1*WW + ix1;

        #pragma unroll
        for (int ci = 0; ci < 3; ci++) {
            const float* xc = xb + ci * PLANE;
            float tap = w00 * __ldg(xc + i00) + w01 * __ldg(xc + i01)
                      + w10 * __ldg(xc + i10) + w11 * __ldg(xc + i11);
            consume_tap(s_w + (27 + ci*9 + k)*64, tap, acc);
        }
    }

    // ---- epilogue: bias + coalesced stores (64 channels, 1 pixel) ----
    float* o = out + (size_t)b * COUT * PLANE + (size_t)h * WW + w;
    #pragma unroll
    for (int i = 0; i < 32; i++) {
        ull v = add2(acc[i], s_bpair[i]);
        o[(size_t)(2*i)   * PLANE] = lo32(v);
        o[(size_t)(2*i+1) * PLANE] = hi32(v);
    }
}

// ---------------------------------------------------------------------------
// Kernel B: deterministic per-(b,c,half) partial sums over y
// ---------------------------------------------------------------------------
__global__ __launch_bounds__(256)
void reduce_kernel(const float* __restrict__ y)
{
    const int blk  = blockIdx.x;         // b*128 + c*2 + half
    const int half = blk & 1;
    const int c    = (blk >> 1) & 63;
    const int b    = blk >> 7;
    const float4* p = reinterpret_cast<const float4*>(
        y + ((size_t)b*COUT + c) * PLANE + (size_t)half * (PLANE/2));
    const int tid = threadIdx.x;
    float s = 0.f, q = 0.f;
    #pragma unroll 4
    for (int i = tid; i < PLANE/8; i += 256) {
        float4 v = p[i];
        s += (v.x + v.y) + (v.z + v.w);
        q += (v.x*v.x + v.y*v.y) + (v.z*v.z + v.w*v.w);
    }
    __shared__ float ss[256], sq[256];
    ss[tid] = s; sq[tid] = q;
    __syncthreads();
    for (int st = 128; st > 0; st >>= 1) {
        if (tid < st) { ss[tid] += ss[tid+st]; sq[tid] += sq[tid+st]; }
        __syncthreads();
    }
    if (tid == 0) {
        g_partS[c*32 + b*2 + half] = ss[0];
        g_partQ[c*32 + b*2 + half] = sq[0];
    }
}

// ---------------------------------------------------------------------------
// Kernel C: finalize stats
// ---------------------------------------------------------------------------
__global__ void stats_kernel(const float* __restrict__ gamma,
                             const float* __restrict__ beta)
{
    const int c = threadIdx.x;
    if (c >= COUT) return;
    float s = 0.f, q = 0.f;
    #pragma unroll
    for (int i = 0; i < 32; i++) { s += g_partS[c*32 + i]; q += g_partQ[c*32 + i]; }
    const float invN = 1.f / (float)NPIX;
    float mean = s * invN;
    float var  = q * invN - mean * mean;
    float inv  = rsqrtf(var + 1e-5f);
    float sc   = gamma[c] * inv;
    g_scale[c] = sc;
    g_shift[c] = beta[c] - mean * sc;
}

// ---------------------------------------------------------------------------
// Kernel D: in-place normalize + SiLU
// ---------------------------------------------------------------------------
#define N4TOT ((size_t)BB*COUT*PLANE/4)
#define N4HALF (N4TOT/2)

__global__ __launch_bounds__(256)
void norm_silu(float* __restrict__ y)
{
    const size_t i0 = (size_t)blockIdx.x * 256 + threadIdx.x;
    float4* yp = reinterpret_cast<float4*>(y);
    #pragma unroll
    for (int r = 0; r < 2; r++) {
        size_t idx = i0 + (size_t)r * N4HALF;
        int c = (int)((idx >> 14) & 63);
        float sc = g_scale[c];
        float sh = g_shift[c];
        float4 v = yp[idx];
        float t0 = fmaf(v.x, sc, sh);
        float t1 = fmaf(v.y, sc, sh);
        float t2 = fmaf(v.z, sc, sh);
        float t3 = fmaf(v.w, sc, sh);
        v.x = t0 / (1.f + __expf(-t0));
        v.y = t1 / (1.f + __expf(-t1));
        v.z = t2 / (1.f + __expf(-t2));
        v.w = t3 / (1.f + __expf(-t3));
        yp[idx] = v;
    }
}

// ---------------------------------------------------------------------------
extern "C" void kernel_launch(void* const* d_in, const int* in_sizes, int n_in,
                              void* d_out, int out_size)
{
    const float* x      = (const float*)d_in[0];
    const float* w_off  = (const float*)d_in[1];
    const float* b_off  = (const float*)d_in[2];
    const float* w_dcn  = (const float*)d_in[3];
    const float* w_conv = (const float*)d_in[4];
    const float* b_conv = (const float*)d_in[5];
    const float* gamma  = (const float*)d_in[6];
    const float* beta   = (const float*)d_in[7];
    float* out = (float*)d_out;

    fused_main<<<NBLK, 256>>>(x, w_off, b_off, w_dcn, w_conv, b_conv, out);
    reduce_kernel<<<BB*COUT*2, 256>>>(out);
    stats_kernel<<<1, 64>>>(gamma, beta);
    norm_silu<<<N4HALF/256, 256>>>(out);
}

// round 6
// speedup vs baseline: 1.3261x; 1.3261x over previous
#include <cuda_runtime.h>
#include <cuda_bf16.h>
#include <cstdint>

#define BB 16
#define CIN 3
#define HH 256
#define WW 256
#define COUT 64
#define NPIX (BB*HH*WW)
#define PLANE (HH*WW)
#define NBLK (BB*HH)              // 4096 row-blocks

typedef unsigned long long ull;

// BN partials: [channel][block]
__device__ float g_partS[COUT * NBLK];
__device__ float g_partQ[COUT * NBLK];
__device__ float g_scale[COUT];
__device__ float g_shift[COUT];

// ---- dynamic SMEM layout (bytes) ----
#define WA_STRIDE 57
#define TAP_STRIDE 264
#define OFF_WA   0                             // float[64][57]      14592 (tf32)
#define OFF_TAPS (OFF_WA + 64*WA_STRIDE*4)     // float[56][264]     59136 (tf32)
#define OFF_X    (OFF_TAPS + 56*TAP_STRIDE*4)  // float[3][3][264]    9504
#define OFF_WOFF (OFF_X + 3*3*264*4)           // float[18][32]       2304
#define OFF_BIAS (OFF_WOFF + 18*32*4)          // float[64]            256
#define OFF_REDS (OFF_BIAS + 64*4)             // float[64][8]        2048
#define OFF_REDQ (OFF_REDS + 64*8*4)           // float[64][8]        2048
#define SMEM_BYTES (OFF_REDQ + 64*8*4)         // = 89888

__device__ __forceinline__ void fma2(ull& a, ull b, ull c) {
    asm("fma.rn.f32x2 %0, %1, %2, %0;" : "+l"(a) : "l"(b), "l"(c));
}
__device__ __forceinline__ ull pack2(float a, float b) {
    ull r; asm("mov.b64 %0, {%1, %2};" : "=l"(r) : "r"(__float_as_uint(a)), "r"(__float_as_uint(b))); return r;
}
__device__ __forceinline__ float lo32(ull v) { return __uint_as_float((unsigned)v); }
__device__ __forceinline__ float hi32(ull v) { return __uint_as_float((unsigned)(v >> 32)); }
__device__ __forceinline__ float tf32r(float f) {
    unsigned u; asm("cvt.rna.tf32.f32 %0, %1;" : "=r"(u) : "f"(f));
    return __uint_as_float(u);
}
__device__ __forceinline__ void mma_tf32(float* d, const unsigned* a, const unsigned* b) {
    asm("mma.sync.aligned.m16n8k8.row.col.f32.tf32.tf32.f32 "
        "{%0,%1,%2,%3}, {%4,%5,%6,%7}, {%8,%9}, {%0,%1,%2,%3};"
        : "+f"(d[0]), "+f"(d[1]), "+f"(d[2]), "+f"(d[3])
        : "r"(a[0]), "r"(a[1]), "r"(a[2]), "r"(a[3]), "r"(b[0]), "r"(b[1]));
}

// ---------------------------------------------------------------------------
// Kernel A: phase 1 builds tf32 taps in SMEM (offset conv + bilinear via L2);
// phase 2 does the [64ch x 56k] x [56k x 256px] GEMM on tensor cores.
// One block = one (b,h) row of 256 pixels. Fused BN partials.
// ---------------------------------------------------------------------------
__global__ __launch_bounds__(256, 2)
void fused_main(const float* __restrict__ x,
                const float* __restrict__ w_off,
                const float* __restrict__ b_off,
                const float* __restrict__ w_dcn,
                const float* __restrict__ w_conv,
                const float* __restrict__ b_conv,
                float* __restrict__ out)
{
    extern __shared__ __align__(16) char smem[];
    float* s_wA   = (float*)(smem + OFF_WA);    // [ch*57 + k], tf32
    float* s_taps = (float*)(smem + OFF_TAPS);  // [k*264 + px], tf32
    float* s_x    = (float*)(smem + OFF_X);     // [(ci*3+r)*264 + col+1]
    float* s_woff = (float*)(smem + OFF_WOFF);  // [o*32 + j]
    float* s_bias = (float*)(smem + OFF_BIAS);
    float* s_redS = (float*)(smem + OFF_REDS);  // [ch*8 + warp]
    float* s_redQ = (float*)(smem + OFF_REDQ);
    __shared__ float s_boff[18];

    const int tid  = threadIdx.x;
    const int bidx = blockIdx.x;
    const int b    = bidx >> 8;
    const int h    = bidx & 255;

    // ---- stage A (weights, tf32) ----
    for (int i = tid; i < 64*WA_STRIDE; i += 256) {
        int c = i / WA_STRIDE, k = i % WA_STRIDE;
        float v = 0.f;
        if (k < 27)       v = w_conv[c*27 + k];
        else if (k < 54)  v = w_dcn[c*27 + (k - 27)];
        s_wA[i] = tf32r(v);
    }
    // zero pad rows 54,55 of taps
    for (int i = tid; i < 2*TAP_STRIDE; i += 256)
        s_taps[54*TAP_STRIDE + i] = 0.f;
    for (int i = tid; i < 18*32; i += 256) {
        int o = i >> 5, j = i & 31;
        s_woff[i] = (j < 27) ? w_off[o*27 + j] : 0.f;
    }
    if (tid < 64) s_bias[tid] = b_conv[tid];
    if (tid < 18) s_boff[tid] = b_off[tid];

    // ---- stage x rows h-1..h+1 with 1-col halo ----
    for (int i = tid; i < 3*3*258; i += 256) {
        int ci = i / (3*258);
        int r  = (i / 258) % 3;
        int cc = i % 258;
        int gy = h - 1 + r;
        int gx = cc - 1;
        float v = 0.f;
        if (gy >= 0 && gy < HH && gx >= 0 && gx < WW)
            v = x[((size_t)(b*3 + ci)*HH + gy)*WW + gx];
        s_x[(ci*3 + r)*264 + cc] = v;
    }
    __syncthreads();

    // ================= Phase 1: taps for pixel w = tid =================
    {
        const int w = tid;
        float fv[27];
        #pragma unroll
        for (int ci = 0; ci < 3; ci++)
            #pragma unroll
            for (int k = 0; k < 9; k++)
                fv[ci*9 + k] = s_x[(ci*3 + k/3)*264 + w + (k%3)];

        #pragma unroll
        for (int k = 0; k < 27; k++)
            s_taps[k*TAP_STRIDE + w] = tf32r(fv[k]);

        // pack for offset conv (full fp32)
        ull fvp[14];
        #pragma unroll
        for (int qq = 0; qq < 13; qq++) fvp[qq] = pack2(fv[2*qq], fv[2*qq+1]);
        fvp[13] = pack2(fv[26], 0.f);

        const float* xb = x + (size_t)b * 3 * PLANE;
        #pragma unroll 1
        for (int k = 0; k < 9; k++) {
            ull ay = 0ULL, ax = 0ULL;
            const ulonglong2* wyp = reinterpret_cast<const ulonglong2*>(s_woff + (2*k)*32);
            const ulonglong2* wxp = reinterpret_cast<const ulonglong2*>(s_woff + (2*k+1)*32);
            #pragma unroll
            for (int v = 0; v < 7; v++) {
                ulonglong2 a = wyp[v];
                ulonglong2 c = wxp[v];
                fma2(ay, a.x, fvp[2*v]);
                fma2(ay, a.y, fvp[2*v+1]);
                fma2(ax, c.x, fvp[2*v]);
                fma2(ax, c.y, fvp[2*v+1]);
            }
            float dy = lo32(ay) + hi32(ay) + s_boff[2*k];
            float dx = lo32(ax) + hi32(ax) + s_boff[2*k+1];

            const int ky = k / 3, kx = k - 3*ky;
            float py = (float)(h + ky - 1) + dy;
            float px = (float)(w + kx - 1) + dx;
            float y0 = floorf(py), x0 = floorf(px);
            float ly = py - y0,    lx = px - x0;
            float hy = 1.f - ly,   hx = 1.f - lx;
            float y1 = y0 + 1.f,   x1 = x0 + 1.f;
            bool vy0 = (y0 >= 0.f) && (y0 <= 255.f);
            bool vy1 = (y1 >= 0.f) && (y1 <= 255.f);
            bool vx0 = (x0 >= 0.f) && (x0 <= 255.f);
            bool vx1 = (x1 >= 0.f) && (x1 <= 255.f);
            float w00 = hy*hx * ((vy0 && vx0) ? 1.f : 0.f);
            float w01 = hy*lx * ((vy0 && vx1) ? 1.f : 0.f);
            float w10 = ly*hx * ((vy1 && vx0) ? 1.f : 0.f);
            float w11 = ly*lx * ((vy1 && vx1) ? 1.f : 0.f);
            int iy0 = min(max((int)y0, 0), 255);
            int iy1 = min(max((int)y1, 0), 255);
            int ix0 = min(max((int)x0, 0), 255);
            int ix1 = min(max((int)x1, 0), 255);
            int i00 = iy0*WW + ix0, i01 = iy0*WW + ix1;
            int i10 = iy1*WW + ix0, i11 = iy1*WW + ix1;
            #pragma unroll
            for (int ci = 0; ci < 3; ci++) {
                const float* xc = xb + ci * PLANE;
                float tap = w00 * __ldg(xc + i00) + w01 * __ldg(xc + i01)
                          + w10 * __ldg(xc + i10) + w11 * __ldg(xc + i11);
                s_taps[(27 + ci*9 + k)*TAP_STRIDE + w] = tf32r(tap);
            }
        }
    }
    __syncthreads();

    // ================= Phase 2: tensor-core GEMM =================
    const int wid  = tid >> 5;
    const int lane = tid & 31;
    const int g    = lane >> 2;     // 0..7
    const int q    = lane & 3;      // 0..3
    const int pxw  = wid << 5;      // warp's 32-pixel base

    float C[4][4][4];
    #pragma unroll
    for (int m = 0; m < 4; m++)
        #pragma unroll
        for (int n = 0; n < 4; n++)
            #pragma unroll
            for (int r = 0; r < 4; r++) C[m][n][r] = 0.f;

    #pragma unroll
    for (int kt = 0; kt < 7; kt++) {
        const int kb = kt << 3;
        unsigned A[4][4];
        #pragma unroll
        for (int m = 0; m < 4; m++) {
            const float* ap = s_wA + (m*16 + g)*WA_STRIDE + kb + q;
            A[m][0] = __float_as_uint(ap[0]);
            A[m][1] = __float_as_uint(ap[8*WA_STRIDE]);
            A[m][2] = __float_as_uint(ap[4]);
            A[m][3] = __float_as_uint(ap[8*WA_STRIDE + 4]);
        }
        unsigned Bf[4][2];
        #pragma unroll
        for (int n = 0; n < 4; n++) {
            const float* bp = s_taps + (kb + q)*TAP_STRIDE + pxw + (n << 3) + g;
            Bf[n][0] = __float_as_uint(bp[0]);
            Bf[n][1] = __float_as_uint(bp[4*TAP_STRIDE]);
        }
        #pragma unroll
        for (int m = 0; m < 4; m++)
            #pragma unroll
            for (int n = 0; n < 4; n++)
                mma_tf32(C[m][n], A[m], Bf[n]);
    }

    // ---- epilogue: bias, store, BN partials ----
    float* outbh = out + (size_t)b * COUT * PLANE + (size_t)h * WW;
    #pragma unroll
    for (int m = 0; m < 4; m++) {
        const int ch0 = m*16 + g;
        const int ch1 = ch0 + 8;
        const float b0v = s_bias[ch0];
        const float b1v = s_bias[ch1];
        float s0 = 0.f, q0 = 0.f, s1 = 0.f, q1 = 0.f;
        #pragma unroll
        for (int n = 0; n < 4; n++) {
            float c0 = C[m][n][0] + b0v, c1 = C[m][n][1] + b0v;
            float c2 = C[m][n][2] + b1v, c3 = C[m][n][3] + b1v;
            const int px = pxw + (n << 3) + (q << 1);
            *reinterpret_cast<float2*>(outbh + (size_t)ch0 * PLANE + px) = make_float2(c0, c1);
            *reinterpret_cast<float2*>(outbh + (size_t)ch1 * PLANE + px) = make_float2(c2, c3);
            s0 += c0 + c1;  q0 += c0*c0 + c1*c1;
            s1 += c2 + c3;  q1 += c2*c2 + c3*c3;
        }
        #pragma unroll
        for (int d = 1; d < 4; d <<= 1) {
            s0 += __shfl_xor_sync(0xffffffffu, s0, d);
            q0 += __shfl_xor_sync(0xffffffffu, q0, d);
            s1 += __shfl_xor_sync(0xffffffffu, s1, d);
            q1 += __shfl_xor_sync(0xffffffffu, q1, d);
        }
        if (q == 0) {
            s_redS[ch0*8 + wid] = s0;  s_redQ[ch0*8 + wid] = q0;
            s_redS[ch1*8 + wid] = s1;  s_redQ[ch1*8 + wid] = q1;
        }
    }
    __syncthreads();

    if (tid < COUT) {
        float s = 0.f, qq = 0.f;
        #pragma unroll
        for (int wdx = 0; wdx < 8; wdx++) {
            s  += s_redS[tid*8 + wdx];
            qq += s_redQ[tid*8 + wdx];
        }
        g_partS[tid*NBLK + bidx] = s;
        g_partQ[tid*NBLK + bidx] = qq;
    }
}

// ---------------------------------------------------------------------------
// Kernel B: per-channel stats finalize
// ---------------------------------------------------------------------------
__global__ __launch_bounds__(256)
void stats_kernel(const float* __restrict__ gamma,
                  const float* __restrict__ beta)
{
    const int c = blockIdx.x;
    const int tid = threadIdx.x;
    float s = 0.f, q = 0.f;
    for (int i = tid; i < NBLK; i += 256) {
        s += g_partS[c*NBLK + i];
        q += g_partQ[c*NBLK + i];
    }
    __shared__ float ss[256], sq[256];
    ss[tid] = s; sq[tid] = q;
    __syncthreads();
    for (int st = 128; st > 0; st >>= 1) {
        if (tid < st) { ss[tid] += ss[tid+st]; sq[tid] += sq[tid+st]; }
        __syncthreads();
    }
    if (tid == 0) {
        const float invN = 1.f / (float)NPIX;
        float mean = ss[0] * invN;
        float var  = sq[0] * invN - mean * mean;
        float inv  = rsqrtf(var + 1e-5f);
        float sc   = gamma[c] * inv;
        g_scale[c] = sc;
        g_shift[c] = beta[c] - mean * sc;
    }
}

// ---------------------------------------------------------------------------
// Kernel C: in-place normalize + SiLU
// ---------------------------------------------------------------------------
#define N4TOT ((size_t)BB*COUT*PLANE/4)
#define N4HALF (N4TOT/2)

__global__ __launch_bounds__(256)
void norm_silu(float* __restrict__ y)
{
    const size_t i0 = (size_t)blockIdx.x * 256 + threadIdx.x;
    float4* yp = reinterpret_cast<float4*>(y);
    #pragma unroll
    for (int r = 0; r < 2; r++) {
        size_t idx = i0 + (size_t)r * N4HALF;
        int c = (int)((idx >> 14) & 63);
        float sc = g_scale[c];
        float sh = g_shift[c];
        float4 v = yp[idx];
        float t0 = fmaf(v.x, sc, sh);
        float t1 = fmaf(v.y, sc, sh);
        float t2 = fmaf(v.z, sc, sh);
        float t3 = fmaf(v.w, sc, sh);
        v.x = t0 / (1.f + __expf(-t0));
        v.y = t1 / (1.f + __expf(-t1));
        v.z = t2 / (1.f + __expf(-t2));
        v.w = t3 / (1.f + __expf(-t3));
        yp[idx] = v;
    }
}

// ---------------------------------------------------------------------------
extern "C" void kernel_launch(void* const* d_in, const int* in_sizes, int n_in,
                              void* d_out, int out_size)
{
    const float* x      = (const float*)d_in[0];
    const float* w_off  = (const float*)d_in[1];
    const float* b_off  = (const float*)d_in[2];
    const float* w_dcn  = (const float*)d_in[3];
    const float* w_conv = (const float*)d_in[4];
    const float* b_conv = (const float*)d_in[5];
    const float* gamma  = (const float*)d_in[6];
    const float* beta   = (const float*)d_in[7];
    float* out = (float*)d_out;

    cudaFuncSetAttribute(fused_main, cudaFuncAttributeMaxDynamicSharedMemorySize, SMEM_BYTES);

    fused_main<<<NBLK, 256, SMEM_BYTES>>>(x, w_off, b_off, w_dcn, w_conv, b_conv, out);
    stats_kernel<<<COUT, 256>>>(gamma, beta);
    norm_silu<<<N4HALF/256, 256>>>(out);
}

// round 7
// speedup vs baseline: 1.6571x; 1.2496x over previous
#include <cuda_runtime.h>
#include <cuda_bf16.h>
#include <cstdint>

#define BB 16
#define CIN 3
#define HH 256
#define WW 256
#define COUT 64
#define NPIX (BB*HH*WW)
#define PLANE (HH*WW)
#define NBLK (BB*HH)              // 4096 row-blocks

typedef unsigned long long ull;

// BN partials: [channel][block]
__device__ float g_partS[COUT * NBLK];
__device__ float g_partQ[COUT * NBLK];
__device__ float g_scale[COUT];
__device__ float g_shift[COUT];

// Pre-packed weights (filled by prep_kernel each launch)
#define WA_STRIDE 57
__device__ float g_wpack[COUT * WA_STRIDE];   // [ch][k] tf32, k<54 real, 54..56 zero
__device__ float g_woffp[18 * 32];            // [o][j] padded, j>=27 zero

// ---- dynamic SMEM layout (bytes) ----
#define TAP_STRIDE 264
#define OFF_WA   0                             // float[64][57]      14592 (tf32)
#define OFF_TAPS (OFF_WA + 64*WA_STRIDE*4)     // float[56][264]     59136 (tf32)
#define OFF_X    (OFF_TAPS + 56*TAP_STRIDE*4)  // float[3][3][264]    9504
#define OFF_WOFF (OFF_X + 3*3*264*4)           // float[18][32]       2304
#define OFF_BIAS (OFF_WOFF + 18*32*4)          // float[64]            256
#define OFF_REDS (OFF_BIAS + 64*4)             // float[64][8]        2048
#define OFF_REDQ (OFF_REDS + 64*8*4)           // float[64][8]        2048
#define SMEM_BYTES (OFF_REDQ + 64*8*4)         // = 89888

__device__ __forceinline__ void fma2(ull& a, ull b, ull c) {
    asm("fma.rn.f32x2 %0, %1, %2, %0;" : "+l"(a) : "l"(b), "l"(c));
}
__device__ __forceinline__ ull pack2(float a, float b) {
    ull r; asm("mov.b64 %0, {%1, %2};" : "=l"(r) : "r"(__float_as_uint(a)), "r"(__float_as_uint(b))); return r;
}
__device__ __forceinline__ float lo32(ull v) { return __uint_as_float((unsigned)v); }
__device__ __forceinline__ float hi32(ull v) { return __uint_as_float((unsigned)(v >> 32)); }
__device__ __forceinline__ float tf32r(float f) {
    unsigned u; asm("cvt.rna.tf32.f32 %0, %1;" : "=r"(u) : "f"(f));
    return __uint_as_float(u);
}
__device__ __forceinline__ void mma_tf32(float* d, const unsigned* a, const unsigned* b) {
    asm("mma.sync.aligned.m16n8k8.row.col.f32.tf32.tf32.f32 "
        "{%0,%1,%2,%3}, {%4,%5,%6,%7}, {%8,%9}, {%0,%1,%2,%3};"
        : "+f"(d[0]), "+f"(d[1]), "+f"(d[2]), "+f"(d[3])
        : "r"(a[0]), "r"(a[1]), "r"(a[2]), "r"(a[3]), "r"(b[0]), "r"(b[1]));
}

// ---------------------------------------------------------------------------
// Prep: pack weights once per launch (runs in ~2us)
// ---------------------------------------------------------------------------
__global__ void prep_kernel(const float* __restrict__ w_off,
                            const float* __restrict__ w_dcn,
                            const float* __restrict__ w_conv)
{
    const int i = blockIdx.x * 256 + threadIdx.x;
    if (i < COUT * WA_STRIDE) {
        int c = i / WA_STRIDE, k = i - c * WA_STRIDE;
        float v = 0.f;
        if (k < 27)       v = w_conv[c*27 + k];
        else if (k < 54)  v = w_dcn[c*27 + (k - 27)];
        g_wpack[i] = tf32r(v);
    }
    if (i < 18*32) {
        int o = i >> 5, j = i & 31;
        g_woffp[i] = (j < 27) ? w_off[o*27 + j] : 0.f;
    }
}

// ---------------------------------------------------------------------------
// Kernel A: phase 1 builds tf32 taps in SMEM; phase 2 = tensor-core GEMM.
// One block = one (b,h) row of 256 pixels. Fused BN partials.
// ---------------------------------------------------------------------------
__global__ __launch_bounds__(256, 2)
void fused_main(const float* __restrict__ x,
                const float* __restrict__ b_off,
                const float* __restrict__ b_conv,
                float* __restrict__ out)
{
    extern __shared__ __align__(16) char smem[];
    float* s_wA   = (float*)(smem + OFF_WA);
    float* s_taps = (float*)(smem + OFF_TAPS);
    float* s_x    = (float*)(smem + OFF_X);
    float* s_woff = (float*)(smem + OFF_WOFF);
    float* s_bias = (float*)(smem + OFF_BIAS);
    float* s_redS = (float*)(smem + OFF_REDS);
    float* s_redQ = (float*)(smem + OFF_REDQ);
    __shared__ float s_boff[18];

    const int tid  = threadIdx.x;
    const int bidx = blockIdx.x;
    const int b    = bidx >> 8;
    const int h    = bidx & 255;

    // ---- linear float4 weight staging (no div/mod) ----
    {
        const float4* src = reinterpret_cast<const float4*>(g_wpack);
        float4* dst = reinterpret_cast<float4*>(s_wA);
        #pragma unroll
        for (int r = 0; r < 4; r++) {
            int i = r*256 + tid;
            if (i < (COUT*WA_STRIDE)/4) dst[i] = src[i];
        }
        const float4* src2 = reinterpret_cast<const float4*>(g_woffp);
        float4* dst2 = reinterpret_cast<float4*>(s_woff);
        if (tid < (18*32)/4) dst2[tid] = src2[tid];
    }
    // zero pad tap rows 54,55
    {
        float4* tz = reinterpret_cast<float4*>(s_taps + 54*TAP_STRIDE);
        #pragma unroll
        for (int r = 0; r < 1; r++) {
            int i = tid;
            if (i < (2*TAP_STRIDE)/4) tz[i] = make_float4(0.f,0.f,0.f,0.f);
        }
        if (tid < 2*TAP_STRIDE - 4*((2*TAP_STRIDE)/4)) {} // (2*264=528 %4==0)
    }
    if (tid < 64) s_bias[tid] = b_conv[tid];
    if (tid < 18) s_boff[tid] = b_off[tid];

    // ---- x staging: 9 rows, thread = column, no division ----
    {
        const float* xb = x + (size_t)b * 3 * PLANE;
        #pragma unroll
        for (int ci = 0; ci < 3; ci++) {
            #pragma unroll
            for (int r = 0; r < 3; r++) {
                const int gy = h - 1 + r;
                const bool rowok = (gy >= 0) && (gy < HH);
                const float* row = xb + ci*PLANE + gy*WW;
                float* dst = s_x + (ci*3 + r)*264;
                // col = tid corresponds to gx = tid-1
                int gx = tid - 1;
                dst[tid] = (rowok && gx >= 0) ? row[gx] : 0.f;
                if (tid < 2) {
                    int gx2 = 255 + tid;
                    dst[256 + tid] = (rowok && gx2 < WW) ? row[gx2] : 0.f;
                }
            }
        }
    }
    __syncthreads();

    // ================= Phase 1: taps for pixel w = tid =================
    {
        const int w = tid;
        float fv[27];
        #pragma unroll
        for (int ci = 0; ci < 3; ci++)
            #pragma unroll
            for (int k = 0; k < 9; k++)
                fv[ci*9 + k] = s_x[(ci*3 + k/3)*264 + w + (k%3)];

        #pragma unroll
        for (int k = 0; k < 27; k++)
            s_taps[k*TAP_STRIDE + w] = tf32r(fv[k]);

        ull fvp[14];
        #pragma unroll
        for (int qq = 0; qq < 13; qq++) fvp[qq] = pack2(fv[2*qq], fv[2*qq+1]);
        fvp[13] = pack2(fv[26], 0.f);

        // ---- batched offset conv: all 9 taps' (dy,dx) first ----
        float dyv[9], dxv[9];
        #pragma unroll
        for (int k = 0; k < 9; k++) {
            ull ay = 0ULL, ax = 0ULL;
            const ulonglong2* wyp = reinterpret_cast<const ulonglong2*>(s_woff + (2*k)*32);
            const ulonglong2* wxp = reinterpret_cast<const ulonglong2*>(s_woff + (2*k+1)*32);
            #pragma unroll
            for (int v = 0; v < 7; v++) {
                ulonglong2 a = wyp[v];
                ulonglong2 c = wxp[v];
                fma2(ay, a.x, fvp[2*v]);
                fma2(ay, a.y, fvp[2*v+1]);
                fma2(ax, c.x, fvp[2*v]);
                fma2(ax, c.y, fvp[2*v+1]);
            }
            dyv[k] = lo32(ay) + hi32(ay) + s_boff[2*k];
            dxv[k] = lo32(ax) + hi32(ax) + s_boff[2*k+1];
        }

        // ---- fully unrolled gather loop: max MLP across 108 loads ----
        const float* xb = x + (size_t)b * 3 * PLANE;
        #pragma unroll
        for (int k = 0; k < 9; k++) {
            const int ky = k / 3, kx = k - 3*ky;
            float py = (float)(h + ky - 1) + dyv[k];
            float px = (float)(w + kx - 1) + dxv[k];
            float y0 = floorf(py), x0 = floorf(px);
            float ly = py - y0,    lx = px - x0;
            float hy = 1.f - ly,   hx = 1.f - lx;
            float y1 = y0 + 1.f,   x1 = x0 + 1.f;
            bool vy0 = (y0 >= 0.f) && (y0 <= 255.f);
            bool vy1 = (y1 >= 0.f) && (y1 <= 255.f);
            bool vx0 = (x0 >= 0.f) && (x0 <= 255.f);
            bool vx1 = (x1 >= 0.f) && (x1 <= 255.f);
            float w00 = hy*hx * ((vy0 && vx0) ? 1.f : 0.f);
            float w01 = hy*lx * ((vy0 && vx1) ? 1.f : 0.f);
            float w10 = ly*hx * ((vy1 && vx0) ? 1.f : 0.f);
            float w11 = ly*lx * ((vy1 && vx1) ? 1.f : 0.f);
            int iy0 = min(max((int)y0, 0), 255);
            int iy1 = min(max((int)y1, 0), 255);
            int ix0 = min(max((int)x0, 0), 255);
            int ix1 = min(max((int)x1, 0), 255);
            int i00 = iy0*WW + ix0, i01 = iy0*WW + ix1;
            int i10 = iy1*WW + ix0, i11 = iy1*WW + ix1;
            #pragma unroll
            for (int ci = 0; ci < 3; ci++) {
                const float* xc = xb + ci * PLANE;
                float tap = w00 * __ldg(xc + i00) + w01 * __ldg(xc + i01)
                          + w10 * __ldg(xc + i10) + w11 * __ldg(xc + i11);
                s_taps[(27 + ci*9 + k)*TAP_STRIDE + w] = tf32r(tap);
            }
        }
    }
    __syncthreads();

    // ================= Phase 2: tensor-core GEMM =================
    const int wid  = tid >> 5;
    const int lane = tid & 31;
    const int g    = lane >> 2;     // 0..7
    const int q    = lane & 3;      // 0..3
    const int pxw  = wid << 5;      // warp's 32-pixel base

    float C[4][4][4];
    #pragma unroll
    for (int m = 0; m < 4; m++)
        #pragma unroll
        for (int n = 0; n < 4; n++)
            #pragma unroll
            for (int r = 0; r < 4; r++) C[m][n][r] = 0.f;

    #pragma unroll
    for (int kt = 0; kt < 7; kt++) {
        const int kb = kt << 3;
        unsigned A[4][4];
        #pragma unroll
        for (int m = 0; m < 4; m++) {
            const float* ap = s_wA + (m*16 + g)*WA_STRIDE + kb + q;
            A[m][0] = __float_as_uint(ap[0]);
            A[m][1] = __float_as_uint(ap[8*WA_STRIDE]);
            A[m][2] = __float_as_uint(ap[4]);
            A[m][3] = __float_as_uint(ap[8*WA_STRIDE + 4]);
        }
        unsigned Bf[4][2];
        #pragma unroll
        for (int n = 0; n < 4; n++) {
            const float* bp = s_taps + (kb + q)*TAP_STRIDE + pxw + (n << 3) + g;
            Bf[n][0] = __float_as_uint(bp[0]);
            Bf[n][1] = __float_as_uint(bp[4*TAP_STRIDE]);
        }
        #pragma unroll
        for (int m = 0; m < 4; m++)
            #pragma unroll
            for (int n = 0; n < 4; n++)
                mma_tf32(C[m][n], A[m], Bf[n]);
    }

    // ---- epilogue: bias, store, BN partials ----
    float* outbh = out + (size_t)b * COUT * PLANE + (size_t)h * WW;
    #pragma unroll
    for (int m = 0; m < 4; m++) {
        const int ch0 = m*16 + g;
        const int ch1 = ch0 + 8;
        const float b0v = s_bias[ch0];
        const float b1v = s_bias[ch1];
        float s0 = 0.f, q0 = 0.f, s1 = 0.f, q1 = 0.f;
        #pragma unroll
        for (int n = 0; n < 4; n++) {
            float c0 = C[m][n][0] + b0v, c1 = C[m][n][1] + b0v;
            float c2 = C[m][n][2] + b1v, c3 = C[m][n][3] + b1v;
            const int px = pxw + (n << 3) + (q << 1);
            *reinterpret_cast<float2*>(outbh + (size_t)ch0 * PLANE + px) = make_float2(c0, c1);
            *reinterpret_cast<float2*>(outbh + (size_t)ch1 * PLANE + px) = make_float2(c2, c3);
            s0 += c0 + c1;  q0 += c0*c0 + c1*c1;
            s1 += c2 + c3;  q1 += c2*c2 + c3*c3;
        }
        #pragma unroll
        for (int d = 1; d < 4; d <<= 1) {
            s0 += __shfl_xor_sync(0xffffffffu, s0, d);
            q0 += __shfl_xor_sync(0xffffffffu, q0, d);
            s1 += __shfl_xor_sync(0xffffffffu, s1, d);
            q1 += __shfl_xor_sync(0xffffffffu, q1, d);
        }
        if (q == 0) {
            s_redS[ch0*8 + wid] = s0;  s_redQ[ch0*8 + wid] = q0;
            s_redS[ch1*8 + wid] = s1;  s_redQ[ch1*8 + wid] = q1;
        }
    }
    __syncthreads();

    if (tid < COUT) {
        float s = 0.f, qq = 0.f;
        #pragma unroll
        for (int wdx = 0; wdx < 8; wdx++) {
            s  += s_redS[tid*8 + wdx];
            qq += s_redQ[tid*8 + wdx];
        }
        g_partS[tid*NBLK + bidx] = s;
        g_partQ[tid*NBLK + bidx] = qq;
    }
}

// ---------------------------------------------------------------------------
// Kernel B: per-channel stats finalize
// ---------------------------------------------------------------------------
__global__ __launch_bounds__(256)
void stats_kernel(const float* __restrict__ gamma,
                  const float* __restrict__ beta)
{
    const int c = blockIdx.x;
    const int tid = threadIdx.x;
    float s = 0.f, q = 0.f;
    for (int i = tid; i < NBLK; i += 256) {
        s += g_partS[c*NBLK + i];
        q += g_partQ[c*NBLK + i];
    }
    __shared__ float ss[256], sq[256];
    ss[tid] = s; sq[tid] = q;
    __syncthreads();
    for (int st = 128; st > 0; st >>= 1) {
        if (tid < st) { ss[tid] += ss[tid+st]; sq[tid] += sq[tid+st]; }
        __syncthreads();
    }
    if (tid == 0) {
        const float invN = 1.f / (float)NPIX;
        float mean = ss[0] * invN;
        float var  = sq[0] * invN - mean * mean;
        float inv  = rsqrtf(var + 1e-5f);
        float sc   = gamma[c] * inv;
        g_scale[c] = sc;
        g_shift[c] = beta[c] - mean * sc;
    }
}

// ---------------------------------------------------------------------------
// Kernel C: in-place normalize + SiLU
// ---------------------------------------------------------------------------
#define N4TOT ((size_t)BB*COUT*PLANE/4)
#define N4HALF (N4TOT/2)

__global__ __launch_bounds__(256)
void norm_silu(float* __restrict__ y)
{
    const size_t i0 = (size_t)blockIdx.x * 256 + threadIdx.x;
    float4* yp = reinterpret_cast<float4*>(y);
    #pragma unroll
    for (int r = 0; r < 2; r++) {
        size_t idx = i0 + (size_t)r * N4HALF;
        int c = (int)((idx >> 14) & 63);
        float sc = g_scale[c];
        float sh = g_shift[c];
        float4 v = yp[idx];
        float t0 = fmaf(v.x, sc, sh);
        float t1 = fmaf(v.y, sc, sh);
        float t2 = fmaf(v.z, sc, sh);
        float t3 = fmaf(v.w, sc, sh);
        v.x = t0 / (1.f + __expf(-t0));
        v.y = t1 / (1.f + __expf(-t1));
        v.z = t2 / (1.f + __expf(-t2));
        v.w = t3 / (1.f + __expf(-t3));
        yp[idx] = v;
    }
}

// ---------------------------------------------------------------------------
extern "C" void kernel_launch(void* const* d_in, const int* in_sizes, int n_in,
                              void* d_out, int out_size)
{
    const float* x      = (const float*)d_in[0];
    const float* w_off  = (const float*)d_in[1];
    const float* b_off  = (const float*)d_in[2];
    const float* w_dcn  = (const float*)d_in[3];
    const float* w_conv = (const float*)d_in[4];
    const float* b_conv = (const float*)d_in[5];
    const float* gamma  = (const float*)d_in[6];
    const float* beta   = (const float*)d_in[7];
    float* out = (float*)d_out;

    cudaFuncSetAttribute(fused_main, cudaFuncAttributeMaxDynamicSharedMemorySize, SMEM_BYTES);

    prep_kernel<<<16, 256>>>(w_off, w_dcn, w_conv);
    fused_main<<<NBLK, 256, SMEM_BYTES>>>(x, b_off, b_conv, out);
    stats_kernel<<<COUT, 256>>>(gamma, beta);
    norm_silu<<<N4HALF/256, 256>>>(out);
}

// round 8
// speedup vs baseline: 1.7075x; 1.0304x over previous
#include <cuda_runtime.h>
#include <cuda_bf16.h>
#include <cstdint>

#define BB 16
#define CIN 3
#define HH 256
#define WW 256
#define COUT 64
#define NPIX (BB*HH*WW)
#define PLANE (HH*WW)
#define NBLK (BB*HH)              // 4096 row-blocks

typedef unsigned long long ull;

// BN partials: [channel][block]
__device__ float g_partS[COUT * NBLK];
__device__ float g_partQ[COUT * NBLK];
__device__ float g_scale[COUT];
__device__ float g_shift[COUT];

// Pre-packed weights (filled by prep_kernel each launch)
#define WA_STRIDE 57
#define WOFFA_STRIDE 36
__device__ float g_wpack[COUT * WA_STRIDE];     // [ch][k] tf32, k<54 real, rest 0
__device__ float g_woffA[32 * WOFFA_STRIDE];    // [row][k] tf32, rows>=18 / k>=27 zero

// ---- dynamic SMEM layout (bytes, 16B aligned) ----
#define TAP_STRIDE 264
#define SOFF_STRIDE 264
#define OFF_WA    0                              // float[64][57]     14592
#define OFF_TAPS  (OFF_WA + 64*WA_STRIDE*4)      // float[56][264]    59136
#define OFF_X     (OFF_TAPS + 56*TAP_STRIDE*4)   // float[3][3][264]   9504 (dead after im2col)
#define OFF_SOFF  OFF_X                          // float[18][264]    19008 (overlays s_x)
#define OFF_WOFFA (OFF_SOFF + 18*SOFF_STRIDE*4)  // float[32][36]      4608
#define OFF_BIAS  (OFF_WOFFA + 32*WOFFA_STRIDE*4) // float[64]           256
#define OFF_REDS  (OFF_BIAS + 64*4)              // float[64][8]       2048
#define OFF_REDQ  (OFF_REDS + 64*8*4)            // float[64][8]       2048
#define SMEM_BYTES (OFF_REDQ + 64*8*4)           // = 101696

__device__ __forceinline__ float tf32r(float f) {
    unsigned u; asm("cvt.rna.tf32.f32 %0, %1;" : "=r"(u) : "f"(f));
    return __uint_as_float(u);
}
__device__ __forceinline__ void mma_tf32(float* d, const unsigned* a, const unsigned* b) {
    asm("mma.sync.aligned.m16n8k8.row.col.f32.tf32.tf32.f32 "
        "{%0,%1,%2,%3}, {%4,%5,%6,%7}, {%8,%9}, {%0,%1,%2,%3};"
        : "+f"(d[0]), "+f"(d[1]), "+f"(d[2]), "+f"(d[3])
        : "r"(a[0]), "r"(a[1]), "r"(a[2]), "r"(a[3]), "r"(b[0]), "r"(b[1]));
}

// ---------------------------------------------------------------------------
// Prep: pack weights once per launch
// ---------------------------------------------------------------------------
__global__ void prep_kernel(const float* __restrict__ w_off,
                            const float* __restrict__ w_dcn,
                            const float* __restrict__ w_conv)
{
    const int i = blockIdx.x * 256 + threadIdx.x;
    if (i < COUT * WA_STRIDE) {
        int c = i / WA_STRIDE, k = i - c * WA_STRIDE;
        float v = 0.f;
        if (k < 27)       v = w_conv[c*27 + k];
        else if (k < 54)  v = w_dcn[c*27 + (k - 27)];
        g_wpack[i] = tf32r(v);
    }
    if (i < 32 * WOFFA_STRIDE) {
        int o = i / WOFFA_STRIDE, j = i - o * WOFFA_STRIDE;
        float v = 0.f;
        if (o < 18 && j < 27) v = w_off[o*27 + j];
        g_woffA[i] = tf32r(v);
    }
}

// ---------------------------------------------------------------------------
// Kernel A: im2col taps -> offset conv on tensor cores -> bilinear gathers ->
// main tensor-core GEMM. One block = one (b,h) row of 256 pixels.
// ---------------------------------------------------------------------------
__global__ __launch_bounds__(256, 2)
void fused_main(const float* __restrict__ x,
                const float* __restrict__ b_off,
                const float* __restrict__ b_conv,
                float* __restrict__ out)
{
    extern __shared__ __align__(16) char smem[];
    float* s_wA    = (float*)(smem + OFF_WA);
    float* s_taps  = (float*)(smem + OFF_TAPS);
    float* s_x     = (float*)(smem + OFF_X);
    float* s_off   = (float*)(smem + OFF_SOFF);
    float* s_woffA = (float*)(smem + OFF_WOFFA);
    float* s_bias  = (float*)(smem + OFF_BIAS);
    float* s_redS  = (float*)(smem + OFF_REDS);
    float* s_redQ  = (float*)(smem + OFF_REDQ);
    __shared__ float s_boff[18];

    const int tid  = threadIdx.x;
    const int bidx = blockIdx.x;
    const int b    = bidx >> 8;
    const int h    = bidx & 255;

    // ---- linear float4 weight staging ----
    {
        const float4* src = reinterpret_cast<const float4*>(g_wpack);
        float4* dst = reinterpret_cast<float4*>(s_wA);
        #pragma unroll
        for (int r = 0; r < 4; r++) {
            int i = r*256 + tid;
            if (i < (COUT*WA_STRIDE)/4) dst[i] = src[i];
        }
        const float4* src2 = reinterpret_cast<const float4*>(g_woffA);
        float4* dst2 = reinterpret_cast<float4*>(s_woffA);
        #pragma unroll
        for (int r = 0; r < 2; r++) {
            int i = r*256 + tid;
            if (i < (32*WOFFA_STRIDE)/4) dst2[i] = src2[i];
        }
    }
    // zero tap rows 27..31 (k-pad for offset GEMM) and 54..55 (main GEMM pad)
    {
        float4* t1 = reinterpret_cast<float4*>(s_taps + 27*TAP_STRIDE);
        for (int i = tid; i < (5*TAP_STRIDE)/4; i += 256) t1[i] = make_float4(0.f,0.f,0.f,0.f);
        float4* t2 = reinterpret_cast<float4*>(s_taps + 54*TAP_STRIDE);
        if (tid < (2*TAP_STRIDE)/4) t2[tid] = make_float4(0.f,0.f,0.f,0.f);
    }
    if (tid < 64) s_bias[tid] = b_conv[tid];
    if (tid < 18) s_boff[tid] = b_off[tid];

    // ---- x staging: 9 rows, thread = column ----
    {
        const float* xb = x + (size_t)b * 3 * PLANE;
        #pragma unroll
        for (int ci = 0; ci < 3; ci++) {
            #pragma unroll
            for (int r = 0; r < 3; r++) {
                const int gy = h - 1 + r;
                const bool rowok = (gy >= 0) && (gy < HH);
                const float* row = xb + ci*PLANE + gy*WW;
                float* dst = s_x + (ci*3 + r)*264;
                int gx = tid - 1;
                dst[tid] = (rowok && gx >= 0) ? row[gx] : 0.f;
                if (tid < 2) {
                    int gx2 = 255 + tid;
                    dst[256 + tid] = (rowok && gx2 < WW) ? row[gx2] : 0.f;
                }
            }
        }
    }
    __syncthreads();

    // ---- im2col: write tf32 taps rows 0..26 ----
    {
        const int w = tid;
        #pragma unroll
        for (int ci = 0; ci < 3; ci++)
            #pragma unroll
            for (int k = 0; k < 9; k++)
                s_taps[(ci*9 + k)*TAP_STRIDE + w] =
                    tf32r(s_x[(ci*3 + k/3)*264 + w + (k%3)]);
    }
    __syncthreads();    // taps 0..31 ready; s_x dead

    const int wid  = tid >> 5;
    const int lane = tid & 31;
    const int g    = lane >> 2;     // 0..7
    const int q    = lane & 3;      // 0..3
    const int pxw  = wid << 5;      // warp's 32-pixel base

    // ================= Offset conv on tensor cores =================
    // D[18 x 256] = Woff[18(pad32) x 27(pad32)] x taps[27(pad32) x 256]
    {
        float Co[2][4][4];
        #pragma unroll
        for (int m = 0; m < 2; m++)
            #pragma unroll
            for (int n = 0; n < 4; n++)
                #pragma unroll
                for (int r = 0; r < 4; r++) Co[m][n][r] = 0.f;

        #pragma unroll
        for (int kt = 0; kt < 4; kt++) {
            const int kb = kt << 3;
            unsigned A[2][4];
            #pragma unroll
            for (int m = 0; m < 2; m++) {
                const float* ap = s_woffA + (m*16 + g)*WOFFA_STRIDE + kb + q;
                A[m][0] = __float_as_uint(ap[0]);
                A[m][1] = __float_as_uint(ap[8*WOFFA_STRIDE]);
                A[m][2] = __float_as_uint(ap[4]);
                A[m][3] = __float_as_uint(ap[8*WOFFA_STRIDE + 4]);
            }
            unsigned Bf[4][2];
            #pragma unroll
            for (int n = 0; n < 4; n++) {
                const float* bp = s_taps + (kb + q)*TAP_STRIDE + pxw + (n << 3) + g;
                Bf[n][0] = __float_as_uint(bp[0]);
                Bf[n][1] = __float_as_uint(bp[4*TAP_STRIDE]);
            }
            #pragma unroll
            for (int m = 0; m < 2; m++)
                #pragma unroll
                for (int n = 0; n < 4; n++)
                    mma_tf32(Co[m][n], A[m], Bf[n]);
        }

        // store valid rows to s_off (rows 0..17)
        #pragma unroll
        for (int n = 0; n < 4; n++) {
            const int px = pxw + (n << 3) + (q << 1);
            // m=0: rows g (0..7) and g+8 (8..15) always valid
            *reinterpret_cast<float2*>(s_off + (size_t)g*SOFF_STRIDE + px)
                = make_float2(Co[0][n][0], Co[0][n][1]);
            *reinterpret_cast<float2*>(s_off + (size_t)(g+8)*SOFF_STRIDE + px)
                = make_float2(Co[0][n][2], Co[0][n][3]);
            // m=1: row 16+g valid only for g<2
            if (g < 2)
                *reinterpret_cast<float2*>(s_off + (size_t)(16+g)*SOFF_STRIDE + px)
                    = make_float2(Co[1][n][0], Co[1][n][1]);
        }
    }
    __syncthreads();

    // ================= Gathers: deform taps rows 27..53 =================
    {
        const int w = tid;
        float dyv[9], dxv[9];
        #pragma unroll
        for (int k = 0; k < 9; k++) {
            dyv[k] = s_off[(2*k)*SOFF_STRIDE + w]   + s_boff[2*k];
            dxv[k] = s_off[(2*k+1)*SOFF_STRIDE + w] + s_boff[2*k+1];
        }

        const float* xb = x + (size_t)b * 3 * PLANE;
        #pragma unroll
        for (int k = 0; k < 9; k++) {
            const int ky = k / 3, kx = k - 3*ky;
            float py = (float)(h + ky - 1) + dyv[k];
            float px = (float)(w + kx - 1) + dxv[k];
            float y0 = floorf(py), x0 = floorf(px);
            float ly = py - y0,    lx = px - x0;
            float hy = 1.f - ly,   hx = 1.f - lx;
            float y1 = y0 + 1.f,   x1 = x0 + 1.f;
            bool vy0 = (y0 >= 0.f) && (y0 <= 255.f);
            bool vy1 = (y1 >= 0.f) && (y1 <= 255.f);
            bool vx0 = (x0 >= 0.f) && (x0 <= 255.f);
            bool vx1 = (x1 >= 0.f) && (x1 <= 255.f);
            float w00 = hy*hx * ((vy0 && vx0) ? 1.f : 0.f);
            float w01 = hy*lx * ((vy0 && vx1) ? 1.f : 0.f);
            float w10 = ly*hx * ((vy1 && vx0) ? 1.f : 0.f);
            float w11 = ly*lx * ((vy1 && vx1) ? 1.f : 0.f);
            int iy0 = min(max((int)y0, 0), 255);
            int iy1 = min(max((int)y1, 0), 255);
            int ix0 = min(max((int)x0, 0), 255);
            int ix1 = min(max((int)x1, 0), 255);
            int i00 = iy0*WW + ix0, i01 = iy0*WW + ix1;
            int i10 = iy1*WW + ix0, i11 = iy1*WW + ix1;
            #pragma unroll
            for (int ci = 0; ci < 3; ci++) {
                const float* xc = xb + ci * PLANE;
                float tap = w00 * __ldg(xc + i00) + w01 * __ldg(xc + i01)
                          + w10 * __ldg(xc + i10) + w11 * __ldg(xc + i11);
                s_taps[(27 + ci*9 + k)*TAP_STRIDE + w] = tf32r(tap);
            }
        }
    }
    __syncthreads();

    // ================= Main tensor-core GEMM =================
    float C[4][4][4];
    #pragma unroll
    for (int m = 0; m < 4; m++)
        #pragma unroll
        for (int n = 0; n < 4; n++)
            #pragma unroll
            for (int r = 0; r < 4; r++) C[m][n][r] = 0.f;

    #pragma unroll
    for (int kt = 0; kt < 7; kt++) {
        const int kb = kt << 3;
        unsigned A[4][4];
        #pragma unroll
        for (int m = 0; m < 4; m++) {
            const float* ap = s_wA + (m*16 + g)*WA_STRIDE + kb + q;
            A[m][0] = __float_as_uint(ap[0]);
            A[m][1] = __float_as_uint(ap[8*WA_STRIDE]);
            A[m][2] = __float_as_uint(ap[4]);
            A[m][3] = __float_as_uint(ap[8*WA_STRIDE + 4]);
        }
        unsigned Bf[4][2];
        #pragma unroll
        for (int n = 0; n < 4; n++) {
            const float* bp = s_taps + (kb + q)*TAP_STRIDE + pxw + (n << 3) + g;
            Bf[n][0] = __float_as_uint(bp[0]);
            Bf[n][1] = __float_as_uint(bp[4*TAP_STRIDE]);
        }
        #pragma unroll
        for (int m = 0; m < 4; m++)
            #pragma unroll
            for (int n = 0; n < 4; n++)
                mma_tf32(C[m][n], A[m], Bf[n]);
    }

    // ---- epilogue: bias, store, BN partials ----
    float* outbh = out + (size_t)b * COUT * PLANE + (size_t)h * WW;
    #pragma unroll
    for (int m = 0; m < 4; m++) {
        const int ch0 = m*16 + g;
        const int ch1 = ch0 + 8;
        const float b0v = s_bias[ch0];
        const float b1v = s_bias[ch1];
        float s0 = 0.f, q0 = 0.f, s1 = 0.f, q1 = 0.f;
        #pragma unroll
        for (int n = 0; n < 4; n++) {
            float c0 = C[m][n][0] + b0v, c1 = C[m][n][1] + b0v;
            float c2 = C[m][n][2] + b1v, c3 = C[m][n][3] + b1v;
            const int px = pxw + (n << 3) + (q << 1);
            *reinterpret_cast<float2*>(outbh + (size_t)ch0 * PLANE + px) = make_float2(c0, c1);
            *reinterpret_cast<float2*>(outbh + (size_t)ch1 * PLANE + px) = make_float2(c2, c3);
            s0 += c0 + c1;  q0 += c0*c0 + c1*c1;
            s1 += c2 + c3;  q1 += c2*c2 + c3*c3;
        }
        #pragma unroll
        for (int d = 1; d < 4; d <<= 1) {
            s0 += __shfl_xor_sync(0xffffffffu, s0, d);
            q0 += __shfl_xor_sync(0xffffffffu, q0, d);
            s1 += __shfl_xor_sync(0xffffffffu, s1, d);
            q1 += __shfl_xor_sync(0xffffffffu, q1, d);
        }
        if (q == 0) {
            s_redS[ch0*8 + wid] = s0;  s_redQ[ch0*8 + wid] = q0;
            s_redS[ch1*8 + wid] = s1;  s_redQ[ch1*8 + wid] = q1;
        }
    }
    __syncthreads();

    if (tid < COUT) {
        float s = 0.f, qq = 0.f;
        #pragma unroll
        for (int wdx = 0; wdx < 8; wdx++) {
            s  += s_redS[tid*8 + wdx];
            qq += s_redQ[tid*8 + wdx];
        }
        g_partS[tid*NBLK + bidx] = s;
        g_partQ[tid*NBLK + bidx] = qq;
    }
}

// ---------------------------------------------------------------------------
// Kernel B: per-channel stats finalize
// ---------------------------------------------------------------------------
__global__ __launch_bounds__(256)
void stats_kernel(const float* __restrict__ gamma,
                  const float* __restrict__ beta)
{
    const int c = blockIdx.x;
    const int tid = threadIdx.x;
    float s = 0.f, q = 0.f;
    for (int i = tid; i < NBLK; i += 256) {
        s += g_partS[c*NBLK + i];
        q += g_partQ[c*NBLK + i];
    }
    __shared__ float ss[256], sq[256];
    ss[tid] = s; sq[tid] = q;
    __syncthreads();
    for (int st = 128; st > 0; st >>= 1) {
        if (tid < st) { ss[tid] += ss[tid+st]; sq[tid] += sq[tid+st]; }
        __syncthreads();
    }
    if (tid == 0) {
        const float invN = 1.f / (float)NPIX;
        float mean = ss[0] * invN;
        float var  = sq[0] * invN - mean * mean;
        float inv  = rsqrtf(var + 1e-5f);
        float sc   = gamma[c] * inv;
        g_scale[c] = sc;
        g_shift[c] = beta[c] - mean * sc;
    }
}

// ---------------------------------------------------------------------------
// Kernel C: in-place normalize + SiLU
// ---------------------------------------------------------------------------
#define N4TOT ((size_t)BB*COUT*PLANE/4)
#define N4HALF (N4TOT/2)

__global__ __launch_bounds__(256)
void norm_silu(float* __restrict__ y)
{
    const size_t i0 = (size_t)blockIdx.x * 256 + threadIdx.x;
    float4* yp = reinterpret_cast<float4*>(y);
    #pragma unroll
    for (int r = 0; r < 2; r++) {
        size_t idx = i0 + (size_t)r * N4HALF;
        int c = (int)((idx >> 14) & 63);
        float sc = g_scale[c];
        float sh = g_shift[c];
        float4 v = yp[idx];
        float t0 = fmaf(v.x, sc, sh);
        float t1 = fmaf(v.y, sc, sh);
        float t2 = fmaf(v.z, sc, sh);
        float t3 = fmaf(v.w, sc, sh);
        v.x = t0 / (1.f + __expf(-t0));
        v.y = t1 / (1.f + __expf(-t1));
        v.z = t2 / (1.f + __expf(-t2));
        v.w = t3 / (1.f + __expf(-t3));
        yp[idx] = v;
    }
}

// ---------------------------------------------------------------------------
extern "C" void kernel_launch(void* const* d_in, const int* in_sizes, int n_in,
                              void* d_out, int out_size)
{
    const float* x      = (const float*)d_in[0];
    const float* w_off  = (const float*)d_in[1];
    const float* b_off  = (const float*)d_in[2];
    const float* w_dcn  = (const float*)d_in[3];
    const float* w_conv = (const float*)d_in[4];
    const float* b_conv = (const float*)d_in[5];
    const float* gamma  = (const float*)d_in[6];
    const float* beta   = (const float*)d_in[7];
    float* out = (float*)d_out;

    cudaFuncSetAttribute(fused_main, cudaFuncAttributeMaxDynamicSharedMemorySize, SMEM_BYTES);

    prep_kernel<<<16, 256>>>(w_off, w_dcn, w_conv);
    fused_main<<<NBLK, 256, SMEM_BYTES>>>(x, b_off, b_conv, out);
    stats_kernel<<<COUT, 256>>>(gamma, beta);
    norm_silu<<<N4HALF/256, 256>>>(out);
}

// round 9
// speedup vs baseline: 1.7784x; 1.0415x over previous
#include <cuda_runtime.h>
#include <cuda_bf16.h>
#include <cstdint>

#define BB 16
#define CIN 3
#define HH 256
#define WW 256
#define COUT 64
#define NPIX (BB*HH*WW)
#define PLANE (HH*WW)
#define NBLK (BB*HH)              // 4096 row-blocks

// BN partials: [channel][block]
__device__ float g_partS[COUT * NBLK];
__device__ float g_partQ[COUT * NBLK];
__device__ float g_scale[COUT];
__device__ float g_shift[COUT];

// Pre-packed weights (filled by prep_kernel each launch)
#define WA_STRIDE 57
#define WOFFA_STRIDE 36
__device__ float g_wpack[COUT * WA_STRIDE];     // [ch][k] tf32, k<54 real, rest 0
__device__ float g_woffA[32 * WOFFA_STRIDE];    // [row][k] tf32, rows>=18 / k>=27 zero

// ---- dynamic SMEM layout (bytes, 16B aligned) ----
#define TAP_STRIDE 264
#define OFF_WA    0                               // float[64][57]     14592
#define OFF_TAPS  (OFF_WA + 64*WA_STRIDE*4)       // float[56][264]    59136
#define OFF_X     (OFF_TAPS + 56*TAP_STRIDE*4)    // float[3][3][264]   9504
#define OFF_OFFW  (OFF_X + 3*3*264*4)             // float[8][18][32]  18432 (warp-private)
#define OFF_WOFFA (OFF_OFFW + 8*18*32*4)          // float[32][36]      4608
#define OFF_BIAS  (OFF_WOFFA + 32*WOFFA_STRIDE*4) // float[64]            256
#define OFF_REDS  (OFF_BIAS + 64*4)               // float[64][8]        2048
#define OFF_REDQ  (OFF_REDS + 64*8*4)             // float[64][8]        2048
#define SMEM_BYTES (OFF_REDQ + 64*8*4)            // = 110624

__device__ __forceinline__ float tf32r(float f) {
    unsigned u; asm("cvt.rna.tf32.f32 %0, %1;" : "=r"(u) : "f"(f));
    return __uint_as_float(u);
}
__device__ __forceinline__ void mma_tf32(float* d, const unsigned* a, const unsigned* b) {
    asm("mma.sync.aligned.m16n8k8.row.col.f32.tf32.tf32.f32 "
        "{%0,%1,%2,%3}, {%4,%5,%6,%7}, {%8,%9}, {%0,%1,%2,%3};"
        : "+f"(d[0]), "+f"(d[1]), "+f"(d[2]), "+f"(d[3])
        : "r"(a[0]), "r"(a[1]), "r"(a[2]), "r"(a[3]), "r"(b[0]), "r"(b[1]));
}

// ---------------------------------------------------------------------------
// Prep: pack weights once per launch
// ---------------------------------------------------------------------------
__global__ void prep_kernel(const float* __restrict__ w_off,
                            const float* __restrict__ w_dcn,
                            const float* __restrict__ w_conv)
{
    const int i = blockIdx.x * 256 + threadIdx.x;
    if (i < COUT * WA_STRIDE) {
        int c = i / WA_STRIDE, k = i - c * WA_STRIDE;
        float v = 0.f;
        if (k < 27)       v = w_conv[c*27 + k];
        else if (k < 54)  v = w_dcn[c*27 + (k - 27)];
        g_wpack[i] = tf32r(v);
    }
    if (i < 32 * WOFFA_STRIDE) {
        int o = i / WOFFA_STRIDE, j = i - o * WOFFA_STRIDE;
        float v = 0.f;
        if (o < 18 && j < 27) v = w_off[o*27 + j];
        g_woffA[i] = tf32r(v);
    }
}

// ---------------------------------------------------------------------------
// Kernel A: warp-pipelined. After one staging sync, each warp independently:
// im2col -> offset MMA -> gathers -> main MMA -> epilogue. Final sync only
// for the cross-warp BN reduce.
// ---------------------------------------------------------------------------
__global__ __launch_bounds__(256, 2)
void fused_main(const float* __restrict__ x,
                const float* __restrict__ b_off,
                const float* __restrict__ b_conv,
                float* __restrict__ out)
{
    extern __shared__ __align__(16) char smem[];
    float* s_wA    = (float*)(smem + OFF_WA);
    float* s_taps  = (float*)(smem + OFF_TAPS);
    float* s_x     = (float*)(smem + OFF_X);
    float* s_offw  = (float*)(smem + OFF_OFFW);    // [wid][18][32]
    float* s_woffA = (float*)(smem + OFF_WOFFA);
    float* s_bias  = (float*)(smem + OFF_BIAS);
    float* s_redS  = (float*)(smem + OFF_REDS);
    float* s_redQ  = (float*)(smem + OFF_REDQ);
    __shared__ float s_boff[18];

    const int tid  = threadIdx.x;
    const int bidx = blockIdx.x;
    const int b    = bidx >> 8;
    const int h    = bidx & 255;

    // ---- linear float4 weight staging ----
    {
        const float4* src = reinterpret_cast<const float4*>(g_wpack);
        float4* dst = reinterpret_cast<float4*>(s_wA);
        #pragma unroll
        for (int r = 0; r < 4; r++) {
            int i = r*256 + tid;
            if (i < (COUT*WA_STRIDE)/4) dst[i] = src[i];
        }
        const float4* src2 = reinterpret_cast<const float4*>(g_woffA);
        float4* dst2 = reinterpret_cast<float4*>(s_woffA);
        #pragma unroll
        for (int r = 0; r < 2; r++) {
            int i = r*256 + tid;
            if (i < (32*WOFFA_STRIDE)/4) dst2[i] = src2[i];
        }
    }
    // zero tap rows 27..31 (k-pad for offset GEMM) and 54..55 (main GEMM pad)
    {
        float4* t1 = reinterpret_cast<float4*>(s_taps + 27*TAP_STRIDE);
        for (int i = tid; i < (5*TAP_STRIDE)/4; i += 256) t1[i] = make_float4(0.f,0.f,0.f,0.f);
        float4* t2 = reinterpret_cast<float4*>(s_taps + 54*TAP_STRIDE);
        if (tid < (2*TAP_STRIDE)/4) t2[tid] = make_float4(0.f,0.f,0.f,0.f);
    }
    if (tid < 64) s_bias[tid] = b_conv[tid];
    if (tid < 18) s_boff[tid] = b_off[tid];

    // ---- x staging: 9 rows, thread = column ----
    {
        const float* xb = x + (size_t)b * 3 * PLANE;
        #pragma unroll
        for (int ci = 0; ci < 3; ci++) {
            #pragma unroll
            for (int r = 0; r < 3; r++) {
                const int gy = h - 1 + r;
                const bool rowok = (gy >= 0) && (gy < HH);
                const float* row = xb + ci*PLANE + gy*WW;
                float* dst = s_x + (ci*3 + r)*264;
                int gx = tid - 1;
                dst[tid] = (rowok && gx >= 0) ? row[gx] : 0.f;
                if (tid < 2) {
                    int gx2 = 255 + tid;
                    dst[256 + tid] = (rowok && gx2 < WW) ? row[gx2] : 0.f;
                }
            }
        }
    }
    __syncthreads();   // the ONLY pre-epilogue block-wide sync

    const int wid  = tid >> 5;
    const int lane = tid & 31;
    const int g    = lane >> 2;     // 0..7
    const int q    = lane & 3;      // 0..3
    const int pxw  = wid << 5;      // warp's 32-pixel base
    float* offw    = s_offw + wid * (18*32);

    // ---- im2col: thread w writes tf32 tap column w, rows 0..26 ----
    {
        const int w = tid;
        #pragma unroll
        for (int ci = 0; ci < 3; ci++)
            #pragma unroll
            for (int k = 0; k < 9; k++)
                s_taps[(ci*9 + k)*TAP_STRIDE + w] =
                    tf32r(s_x[(ci*3 + k/3)*264 + w + (k%3)]);
    }
    __syncwarp();

    // ================= Offset conv on tensor cores (warp-local) =============
    {
        float Co[2][4][4];
        #pragma unroll
        for (int m = 0; m < 2; m++)
            #pragma unroll
            for (int n = 0; n < 4; n++)
                #pragma unroll
                for (int r = 0; r < 4; r++) Co[m][n][r] = 0.f;

        #pragma unroll
        for (int kt = 0; kt < 4; kt++) {
            const int kb = kt << 3;
            unsigned A[2][4];
            #pragma unroll
            for (int m = 0; m < 2; m++) {
                const float* ap = s_woffA + (m*16 + g)*WOFFA_STRIDE + kb + q;
                A[m][0] = __float_as_uint(ap[0]);
                A[m][1] = __float_as_uint(ap[8*WOFFA_STRIDE]);
                A[m][2] = __float_as_uint(ap[4]);
                A[m][3] = __float_as_uint(ap[8*WOFFA_STRIDE + 4]);
            }
            unsigned Bf[4][2];
            #pragma unroll
            for (int n = 0; n < 4; n++) {
                const float* bp = s_taps + (kb + q)*TAP_STRIDE + pxw + (n << 3) + g;
                Bf[n][0] = __float_as_uint(bp[0]);
                Bf[n][1] = __float_as_uint(bp[4*TAP_STRIDE]);
            }
            #pragma unroll
            for (int m = 0; m < 2; m++)
                #pragma unroll
                for (int n = 0; n < 4; n++)
                    mma_tf32(Co[m][n], A[m], Bf[n]);
        }

        // store valid rows (0..17) to warp-private buffer [18][32]
        #pragma unroll
        for (int n = 0; n < 4; n++) {
            const int cw = (n << 3) + (q << 1);
            *reinterpret_cast<float2*>(offw + g*32 + cw)
                = make_float2(Co[0][n][0], Co[0][n][1]);
            *reinterpret_cast<float2*>(offw + (g+8)*32 + cw)
                = make_float2(Co[0][n][2], Co[0][n][3]);
            if (g < 2)
                *reinterpret_cast<float2*>(offw + (16+g)*32 + cw)
                    = make_float2(Co[1][n][0], Co[1][n][1]);
        }
    }
    __syncwarp();

    // ================= Gathers: deform taps rows 27..53 (warp-local) ========
    {
        const int w = tid;
        float dyv[9], dxv[9];
        #pragma unroll
        for (int k = 0; k < 9; k++) {
            dyv[k] = offw[(2*k)*32 + lane]   + s_boff[2*k];
            dxv[k] = offw[(2*k+1)*32 + lane] + s_boff[2*k+1];
        }

        const float* xb = x + (size_t)b * 3 * PLANE;
        #pragma unroll
        for (int k = 0; k < 9; k++) {
            const int ky = k / 3, kx = k - 3*ky;
            float py = (float)(h + ky - 1) + dyv[k];
            float px = (float)(w + kx - 1) + dxv[k];
            float y0 = floorf(py), x0 = floorf(px);
            float ly = py - y0,    lx = px - x0;
            float hy = 1.f - ly,   hx = 1.f - lx;
            float y1 = y0 + 1.f,   x1 = x0 + 1.f;
            bool vy0 = (y0 >= 0.f) && (y0 <= 255.f);
            bool vy1 = (y1 >= 0.f) && (y1 <= 255.f);
            bool vx0 = (x0 >= 0.f) && (x0 <= 255.f);
            bool vx1 = (x1 >= 0.f) && (x1 <= 255.f);
            float w00 = hy*hx * ((vy0 && vx0) ? 1.f : 0.f);
            float w01 = hy*lx * ((vy0 && vx1) ? 1.f : 0.f);
            float w10 = ly*hx * ((vy1 && vx0) ? 1.f : 0.f);
            float w11 = ly*lx * ((vy1 && vx1) ? 1.f : 0.f);
            int iy0 = min(max((int)y0, 0), 255);
            int iy1 = min(max((int)y1, 0), 255);
            int ix0 = min(max((int)x0, 0), 255);
            int ix1 = min(max((int)x1, 0), 255);
            int i00 = iy0*WW + ix0, i01 = iy0*WW + ix1;
            int i10 = iy1*WW + ix0, i11 = iy1*WW + ix1;
            #pragma unroll
            for (int ci = 0; ci < 3; ci++) {
                const float* xc = xb + ci * PLANE;
                float tap = w00 * __ldg(xc + i00) + w01 * __ldg(xc + i01)
                          + w10 * __ldg(xc + i10) + w11 * __ldg(xc + i11);
                s_taps[(27 + ci*9 + k)*TAP_STRIDE + w] = tf32r(tap);
            }
        }
    }
    __syncwarp();

    // ================= Main tensor-core GEMM (warp-local) ==================
    float C[4][4][4];
    #pragma unroll
    for (int m = 0; m < 4; m++)
        #pragma unroll
        for (int n = 0; n < 4; n++)
            #pragma unroll
            for (int r = 0; r < 4; r++) C[m][n][r] = 0.f;

    #pragma unroll
    for (int kt = 0; kt < 7; kt++) {
        const int kb = kt << 3;
        unsigned A[4][4];
        #pragma unroll
        for (int m = 0; m < 4; m++) {
            const float* ap = s_wA + (m*16 + g)*WA_STRIDE + kb + q;
            A[m][0] = __float_as_uint(ap[0]);
            A[m][1] = __float_as_uint(ap[8*WA_STRIDE]);
            A[m][2] = __float_as_uint(ap[4]);
            A[m][3] = __float_as_uint(ap[8*WA_STRIDE + 4]);
        }
        unsigned Bf[4][2];
        #pragma unroll
        for (int n = 0; n < 4; n++) {
            const float* bp = s_taps + (kb + q)*TAP_STRIDE + pxw + (n << 3) + g;
            Bf[n][0] = __float_as_uint(bp[0]);
            Bf[n][1] = __float_as_uint(bp[4*TAP_STRIDE]);
        }
        #pragma unroll
        for (int m = 0; m < 4; m++)
            #pragma unroll
            for (int n = 0; n < 4; n++)
                mma_tf32(C[m][n], A[m], Bf[n]);
    }

    // ---- epilogue: bias, store, BN partials ----
    float* outbh = out + (size_t)b * COUT * PLANE + (size_t)h * WW;
    #pragma unroll
    for (int m = 0; m < 4; m++) {
        const int ch0 = m*16 + g;
        const int ch1 = ch0 + 8;
        const float b0v = s_bias[ch0];
        const float b1v = s_bias[ch1];
        float s0 = 0.f, q0 = 0.f, s1 = 0.f, q1 = 0.f;
        #pragma unroll
        for (int n = 0; n < 4; n++) {
            float c0 = C[m][n][0] + b0v, c1 = C[m][n][1] + b0v;
            float c2 = C[m][n][2] + b1v, c3 = C[m][n][3] + b1v;
            const int px = pxw + (n << 3) + (q << 1);
            *reinterpret_cast<float2*>(outbh + (size_t)ch0 * PLANE + px) = make_float2(c0, c1);
            *reinterpret_cast<float2*>(outbh + (size_t)ch1 * PLANE + px) = make_float2(c2, c3);
            s0 += c0 + c1;  q0 += c0*c0 + c1*c1;
            s1 += c2 + c3;  q1 += c2*c2 + c3*c3;
        }
        #pragma unroll
        for (int d = 1; d < 4; d <<= 1) {
            s0 += __shfl_xor_sync(0xffffffffu, s0, d);
            q0 += __shfl_xor_sync(0xffffffffu, q0, d);
            s1 += __shfl_xor_sync(0xffffffffu, s1, d);
            q1 += __shfl_xor_sync(0xffffffffu, q1, d);
        }
        if (q == 0) {
            s_redS[ch0*8 + wid] = s0;  s_redQ[ch0*8 + wid] = q0;
            s_redS[ch1*8 + wid] = s1;  s_redQ[ch1*8 + wid] = q1;
        }
    }
    __syncthreads();

    if (tid < COUT) {
        float s = 0.f, qq = 0.f;
        #pragma unroll
        for (int wdx = 0; wdx < 8; wdx++) {
            s  += s_redS[tid*8 + wdx];
            qq += s_redQ[tid*8 + wdx];
        }
        g_partS[tid*NBLK + bidx] = s;
        g_partQ[tid*NBLK + bidx] = qq;
    }
}

// ---------------------------------------------------------------------------
// Kernel B: per-channel stats finalize
// ---------------------------------------------------------------------------
__global__ __launch_bounds__(256)
void stats_kernel(const float* __restrict__ gamma,
                  const float* __restrict__ beta)
{
    const int c = blockIdx.x;
    const int tid = threadIdx.x;
    float s = 0.f, q = 0.f;
    for (int i = tid; i < NBLK; i += 256) {
        s += g_partS[c*NBLK + i];
        q += g_partQ[c*NBLK + i];
    }
    __shared__ float ss[256], sq[256];
    ss[tid] = s; sq[tid] = q;
    __syncthreads();
    for (int st = 128; st > 0; st >>= 1) {
        if (tid < st) { ss[tid] += ss[tid+st]; sq[tid] += sq[tid+st]; }
        __syncthreads();
    }
    if (tid == 0) {
        const float invN = 1.f / (float)NPIX;
        float mean = ss[0] * invN;
        float var  = sq[0] * invN - mean * mean;
        float inv  = rsqrtf(var + 1e-5f);
        float sc   = gamma[c] * inv;
        g_scale[c] = sc;
        g_shift[c] = beta[c] - mean * sc;
    }
}

// ---------------------------------------------------------------------------
// Kernel C: in-place normalize + SiLU
// ---------------------------------------------------------------------------
#define N4TOT ((size_t)BB*COUT*PLANE/4)
#define N4HALF (N4TOT/2)

__global__ __launch_bounds__(256)
void norm_silu(float* __restrict__ y)
{
    const size_t i0 = (size_t)blockIdx.x * 256 + threadIdx.x;
    float4* yp = reinterpret_cast<float4*>(y);
    #pragma unroll
    for (int r = 0; r < 2; r++) {
        size_t idx = i0 + (size_t)r * N4HALF;
        int c = (int)((idx >> 14) & 63);
        float sc = g_scale[c];
        float sh = g_shift[c];
        float4 v = yp[idx];
        float t0 = fmaf(v.x, sc, sh);
        float t1 = fmaf(v.y, sc, sh);
        float t2 = fmaf(v.z, sc, sh);
        float t3 = fmaf(v.w, sc, sh);
        v.x = t0 / (1.f + __expf(-t0));
        v.y = t1 / (1.f + __expf(-t1));
        v.z = t2 / (1.f + __expf(-t2));
        v.w = t3 / (1.f + __expf(-t3));
        yp[idx] = v;
    }
}

// ---------------------------------------------------------------------------
extern "C" void kernel_launch(void* const* d_in, const int* in_sizes, int n_in,
                              void* d_out, int out_size)
{
    const float* x      = (const float*)d_in[0];
    const float* w_off  = (const float*)d_in[1];
    const float* b_off  = (const float*)d_in[2];
    const float* w_dcn  = (const float*)d_in[3];
    const float* w_conv = (const float*)d_in[4];
    const float* b_conv = (const float*)d_in[5];
    const float* gamma  = (const float*)d_in[6];
    const float* beta   = (const float*)d_in[7];
    float* out = (float*)d_out;

    cudaFuncSetAttribute(fused_main, cudaFuncAttributeMaxDynamicSharedMemorySize, SMEM_BYTES);

    prep_kernel<<<16, 256>>>(w_off, w_dcn, w_conv);
    fused_main<<<NBLK, 256, SMEM_BYTES>>>(x, b_off, b_conv, out);
    stats_kernel<<<COUT, 256>>>(gamma, beta);
    norm_silu<<<N4HALF/256, 256>>>(out);
}